// round 12
// baseline (speedup 1.0000x reference)
#include <cuda_runtime.h>
#include <cuda_bf16.h>
#include <cstdint>

#define NN 256
#define LL 256
#define BB 16384

#if defined(__CUDA_ARCH_FEAT_SM103_ALL) || defined(__CUDA_ARCH_FEAT_SM100_ALL) || defined(__CUDA_ARCH_FEAT_SM101_ALL)
#define HAS_TC 1
#else
#define HAS_TC 0
#endif

typedef unsigned long long u64;

// ---------------- scratch ----------------
__device__ float4 g_C[LL * NN];   // packed coeffs (diag.x, diag.y, off.x, off.y)
__device__ __align__(128) __nv_bfloat16 g_Wrh[256 * 256];
__device__ __align__(128) __nv_bfloat16 g_Wrl[256 * 256];
__device__ __align__(128) __nv_bfloat16 g_Wih[256 * 256];
__device__ __align__(128) __nv_bfloat16 g_Wil[256 * 256];

// ---------------- common helpers ----------------
__device__ __forceinline__ uint32_t smem_u32(const void* p) {
    uint32_t a;
    asm("{ .reg .u64 t; cvta.to.shared.u64 t, %1; cvt.u32.u64 %0, t; }" : "=r"(a) : "l"(p));
    return a;
}
__device__ __forceinline__ float2 cmul(float2 a, float2 b) {
    return make_float2(a.x * b.x - a.y * b.y, a.x * b.y + a.y * b.x);
}
union BU { __nv_bfloat162 h; uint32_t u; };
union F2U { float2 f; u64 u; };

#define FMA_F32X2(d, a, b) \
    asm("fma.rn.f32x2 %0, %1, %2, %0;" : "+l"(d) : "l"(a), "l"(b))
#define MUL_F32X2(d, a, b) \
    asm("mul.rn.f32x2 %0, %1, %2;" : "=l"(d) : "l"(a), "l"(b))
__device__ __forceinline__ u64 pack2(float lo, float hi) {
    u64 r; asm("mov.b64 %0, {%1,%2};" : "=l"(r) : "f"(lo), "f"(hi)); return r;
}
__device__ __forceinline__ u64 dup2(float x) {
    u64 r; asm("mov.b64 %0, {%1,%1};" : "=l"(r) : "f"(x)); return r;
}
// complex step: y = v0*d + v1*o, d=(c.x,c.y), o=(c.z,c.w)
__device__ __forceinline__ float2 cfma4(float2 v0, float2 v1, float4 c) {
    u64 w;
    MUL_F32X2(w, dup2(v0.x), pack2(c.x, c.y));
    FMA_F32X2(w, dup2(v0.y), pack2(-c.y, c.x));
    FMA_F32X2(w, dup2(v1.x), pack2(c.z, c.w));
    FMA_F32X2(w, dup2(v1.y), pack2(-c.w, c.z));
    F2U cv; cv.u = w; return cv.f;
}

// ---------------- tcgen05 / async helpers ----------------
#define TCGEN05_ALLOC_CG2(sa, n) \
    asm volatile("tcgen05.alloc.cta_group::2.sync.aligned.shared::cta.b32 [%0], %1;" :: "r"((uint32_t)(sa)), "r"((uint32_t)(n)) : "memory")
#define TCGEN05_DEALLOC_CG2(t, n) \
    asm volatile("tcgen05.dealloc.cta_group::2.sync.aligned.b32 %0, %1;" :: "r"(t), "r"((uint32_t)(n)))
#define TCGEN05_RELINQ_CG2() \
    asm volatile("tcgen05.relinquish_alloc_permit.cta_group::2.sync.aligned;")
#define TCGEN05_COMMIT_MC_CG2(mb, mask) \
    asm volatile("tcgen05.commit.cta_group::2.mbarrier::arrive::one.shared::cluster.multicast::cluster.b64 [%0], %1;" \
        :: "r"((uint32_t)(mb)), "h"((uint16_t)(mask)) : "memory")
#define TCGEN05_WAIT_LD() asm volatile("tcgen05.wait::ld.sync.aligned;" ::: "memory")
#define TCGEN05_FENCE_AFTER() asm volatile("tcgen05.fence::after_thread_sync;" ::: "memory")
#define FENCE_ASYNC_SHARED() asm volatile("fence.proxy.async.shared::cta;" ::: "memory")
#define CLUSTER_SYNC() do { \
    asm volatile("barrier.cluster.arrive.aligned;" ::: "memory"); \
    asm volatile("barrier.cluster.wait.aligned;" ::: "memory"); \
} while (0)

#define MBARRIER_INIT(mb, cnt) \
    asm volatile("mbarrier.init.shared.b64 [%0], %1;" :: "r"((uint32_t)(mb)), "r"((uint32_t)(cnt)) : "memory")
#define MBARRIER_ARRIVE(mb) \
    asm volatile("mbarrier.arrive.shared.b64 _, [%0];" :: "r"((uint32_t)(mb)) : "memory")
#define MBARRIER_ARRIVE_LEADER(mb) \
    asm volatile("{\n\t.reg .b32 la;\n\tand.b32 la, %0, 0xFEFFFFFF;\n\tmbarrier.arrive.shared::cluster.b64 _, [la];\n\t}" \
        :: "r"((uint32_t)(mb)) : "memory")
#define MBARRIER_EXPECT_TX(mb, tx) \
    asm volatile("mbarrier.arrive.expect_tx.shared.b64 _, [%0], %1;" :: "r"((uint32_t)(mb)), "r"((uint32_t)(tx)) : "memory")
#define MBARRIER_WAIT_PARITY(mb, ph) do { \
    uint32_t _mb = (uint32_t)(mb), _ph = (uint32_t)(ph), _done; \
    asm volatile("{\n\t.reg .pred p;\n\tmbarrier.try_wait.parity.acquire.cta.shared::cta.b64 p, [%1], %2;\n\tselp.b32 %0, 1, 0, p;\n\t}" \
        : "=r"(_done) : "r"(_mb), "r"(_ph) : "memory"); \
    if (!_done) { \
        asm volatile("{\n\t.reg .pred P1;\n\tWL_%=:\n\tmbarrier.try_wait.parity.acquire.cta.shared::cta.b64 P1, [%0], %1, 0x989680;\n\t@P1 bra.uni WD_%=;\n\tbra.uni WL_%=;\n\tWD_%=:\n\t}" \
            :: "r"(_mb), "r"(_ph) : "memory"); \
    } } while (0)
#define MBARRIER_WAIT_PARITY_CLU(mb, ph) do { \
    uint32_t _mb = (uint32_t)(mb), _ph = (uint32_t)(ph), _done; \
    asm volatile("{\n\t.reg .pred p;\n\tmbarrier.try_wait.parity.acquire.cluster.shared::cta.b64 p, [%1], %2;\n\tselp.b32 %0, 1, 0, p;\n\t}" \
        : "=r"(_done) : "r"(_mb), "r"(_ph) : "memory"); \
    if (!_done) { \
        asm volatile("{\n\t.reg .pred P1;\n\tWL_%=:\n\tmbarrier.try_wait.parity.acquire.cluster.shared::cta.b64 P1, [%0], %1, 0x989680;\n\t@P1 bra.uni WD_%=;\n\tbra.uni WL_%=;\n\tWD_%=:\n\t}" \
            :: "r"(_mb), "r"(_ph) : "memory"); \
    } } while (0)

#define CP_ASYNC_BULK(dst, src, bytes, mb) \
    asm volatile("cp.async.bulk.shared::cluster.global.mbarrier::complete_tx::bytes [%0], [%1], %2, [%3];" \
        :: "r"((uint32_t)(dst)), "l"(src), "r"((uint32_t)(bytes)), "r"((uint32_t)(mb)) : "memory")

#define TCGEN05_LD_32X32B_X32(r, ta) \
    asm volatile("tcgen05.ld.sync.aligned.32x32b.x32.b32 " \
        "{%0,%1,%2,%3,%4,%5,%6,%7,%8,%9,%10,%11,%12,%13,%14,%15," \
        "%16,%17,%18,%19,%20,%21,%22,%23,%24,%25,%26,%27,%28,%29,%30,%31}, [%32];" \
        : "=r"((r)[0]), "=r"((r)[1]), "=r"((r)[2]), "=r"((r)[3]), "=r"((r)[4]), "=r"((r)[5]), "=r"((r)[6]), "=r"((r)[7]), \
          "=r"((r)[8]), "=r"((r)[9]), "=r"((r)[10]), "=r"((r)[11]), "=r"((r)[12]), "=r"((r)[13]), "=r"((r)[14]), "=r"((r)[15]), \
          "=r"((r)[16]), "=r"((r)[17]), "=r"((r)[18]), "=r"((r)[19]), "=r"((r)[20]), "=r"((r)[21]), "=r"((r)[22]), "=r"((r)[23]), \
          "=r"((r)[24]), "=r"((r)[25]), "=r"((r)[26]), "=r"((r)[27]), "=r"((r)[28]), "=r"((r)[29]), "=r"((r)[30]), "=r"((r)[31]) \
        : "r"(ta))

#define SWZ64(o) ((o) ^ (((o) >> 3) & 0x30))

#if HAS_TC
__device__ __forceinline__ uint32_t elect_one_pred() {
    uint32_t p;
    asm volatile("{\n\t.reg .pred p;\n\telect.sync _|p, 0xFFFFFFFF;\n\tselp.b32 %0, 1, 0, p;\n\t}" : "=r"(p));
    return p;
}
__device__ __forceinline__ uint32_t cluster_rank() {
    uint32_t r; asm("mov.u32 %0, %%cluster_ctarank;" : "=r"(r)); return r;
}
__device__ __forceinline__ uint64_t make_desc_sw64(uint32_t base) {
    return ((uint64_t)4 << 61) | ((uint64_t)1 << 46) | ((uint64_t)32 << 32) | ((uint64_t)1 << 16)
         | (uint64_t)((base >> 4) & 0x3FFF);
}
__device__ __forceinline__ void mma_f16_ss_cg2(uint32_t d, uint64_t ad, uint64_t bd,
                                               uint32_t idesc, uint32_t en) {
    asm volatile(
        "{\n\t.reg .pred p;\n\tsetp.ne.u32 p, %5, 0;\n\t"
        "tcgen05.mma.cta_group::2.kind::f16 [%0], %1, %2, %3, {%4,%4,%4,%4,%4,%4,%4,%4}, p;\n\t}"
        :: "r"(d), "l"(ad), "l"(bd), "r"(idesc), "r"(0u), "r"(en) : "memory");
}
#endif

// ---------------- kernel 1: per-layer MZI coefficients ----------------
__global__ void coeff_kernel(const float* __restrict__ theta,
                             const float* __restrict__ phi) {
    __shared__ float2 ips[NN];
    __shared__ float2 eps[NN];
    __shared__ float2 offs[NN];
    int l = blockIdx.x;
    int n = threadIdx.x;
    const float* th = theta + l * (NN / 2);
    const float* ph = phi + l * (NN / 2);

    {
        float ang = 0.5f * th[n >> 1];
        if (n & 1) ang = -ang;
        float s, c; sincosf(ang, &s, &c);
        ips[n] = make_float2(c, s);
        if (n & 1) eps[n] = make_float2(1.f, 0.f);
        else { float s2, c2; sincosf(ph[n >> 1], &s2, &c2); eps[n] = make_float2(c2, s2); }
    }
    __syncthreads();

    int nm = (n - 1) & (NN - 1), np = (n + 1) & (NN - 1);
    float2 p0 = ips[nm], p1 = ips[n], p2 = ips[np];
    float2 v = make_float2(2.f * p1.x - p2.x - p0.x, 2.f * p1.y - p2.y - p0.y);
    float2 u = make_float2(2.f * p1.x + p2.x + p0.x, 2.f * p1.y + p2.y + p0.y);
    float2 en = eps[n], ep = eps[nm];

    float2 diag = cmul(en, v); diag.x *= 0.25f; diag.y *= 0.25f;
    float2 iu = make_float2(-u.y, u.x);
    float2 off = cmul(ep, iu); off.x *= 0.25f; off.y *= 0.25f;

    offs[n ^ 1] = off;
    __syncthreads();
    float2 o = offs[n];
    g_C[l * NN + n] = make_float4(diag.x, diag.y, o.x, o.y);
}

// ---------------- kernel 2: compose W — FUSED QUADS (1 barrier / 4 layers) ----------
// Layer 0 (s=0) alone; 63 quads (4q+1..4q+4, shifts +1,-1,+1,-1) covering 1..252;
// pair (253,254); layer 255 (s=+1); final right-perm -1.
// Relative stencils (both parities, window base s1 = i-3-odd):
//   y1[t] = cfma(xw[t+1], xw[RXB[t]], C1[j1+t]),  RXB={0,3,2,5,4,7}
//   y2[t] = cfma(y1[t+1], y1[R2B[t]], C2[j2+t]),  R2B={0,3,2,5}
//   y3[t] = cfma(y2[t+1], y2[R3B[t]], C3[j2+t]),  R3B={0,3}
//   y4    = odd ? cfma(y3[1],y3[0],C4[i]) : cfma(y3[0],y3[1],C4[i])
#define RB 2
__global__ __launch_bounds__(NN) void build_w_kernel(const float* __restrict__ gamma) {
    __shared__ float2 bufA[RB][NN];
    __shared__ float2 bufB[RB][NN];
    int i = threadIdx.x;
    int r0 = blockIdx.x * RB;
    const int M = NN - 1;
    int odd = i & 1;

#pragma unroll
    for (int r = 0; r < RB; r++) {
        int j = r0 + r;
        float2 v = make_float2(0.f, 0.f);
        if (i == j) { float s, c; sincosf(gamma[j], &s, &c); v = make_float2(c, s); }
        bufA[r][i] = v;
    }

    // loop-invariant absolute coeff indices
    int jx1[6], jx2[4];
#pragma unroll
    for (int t = 0; t < 6; ++t) jx1[t] = (i - 3 - odd + t) & M;
#pragma unroll
    for (int t = 0; t < 4; ++t) jx2[t] = (i - 1 - odd + t) & M;

    float4 c0 = g_C[i];
    __syncthreads();

    float2 (*A)[NN] = bufA;
    float2 (*Bx)[NN] = bufB;

    // ---- layer 0 (s=0)
#pragma unroll
    for (int r = 0; r < RB; r++)
        Bx[r][i] = cfma4(A[r][i], A[r][i ^ 1], c0);
    __syncthreads();
    { float2 (*t_)[NN] = A; A = Bx; Bx = t_; }

    // quad coefficient loader
    auto loadq = [&](float4* c, int q) {
        const float4* C1 = g_C + (4 * q + 1) * NN;
        const float4* C2 = C1 + NN;
        const float4* C3 = C2 + NN;
        const float4* C4 = C3 + NN;
#pragma unroll
        for (int t = 0; t < 6; ++t) c[t] = C1[jx1[t]];
#pragma unroll
        for (int t = 0; t < 4; ++t) c[6 + t] = C2[jx2[t]];
#pragma unroll
        for (int t = 0; t < 2; ++t) c[10 + t] = C3[jx2[t]];
        c[12] = C4[i];
    };

    // quad compute: consume A, write Bx, sync, swap
    const int RXB[6] = {0, 3, 2, 5, 4, 7};
    const int R2B[4] = {0, 3, 2, 5};
    auto quad = [&](const float4* c) {
#pragma unroll
        for (int r = 0; r < RB; r++) {
            float2 xw[8];
#pragma unroll
            for (int u = 0; u < 8; ++u) xw[u] = A[r][(i - 3 - odd + u) & M];
            float2 y1[6];
#pragma unroll
            for (int t = 0; t < 6; ++t) y1[t] = cfma4(xw[t + 1], xw[RXB[t]], c[t]);
            float2 y2[4];
#pragma unroll
            for (int t = 0; t < 4; ++t) y2[t] = cfma4(y1[t + 1], y1[R2B[t]], c[6 + t]);
            float2 y3a = cfma4(y2[1], y2[0], c[10]);
            float2 y3b = cfma4(y2[2], y2[3], c[11]);
            Bx[r][i] = odd ? cfma4(y3b, y3a, c[12]) : cfma4(y3a, y3b, c[12]);
        }
        __syncthreads();
        float2 (*t_)[NN] = A; A = Bx; Bx = t_;
    };

    // ---- 63 quads with double register-set prefetch
    float4 qA[13], qB[13];
    loadq(qA, 0);
    loadq(qB, 1);
    for (int k = 0; k < 31; ++k) {
        quad(qA);
        loadq(qA, 2 * k + 2);
        quad(qB);
        if (k < 30) loadq(qB, 2 * k + 3);
    }
    quad(qA);   // quad 62 (layers 249..252)

    // ---- pair (253, 254): shifts (+1, -1)
    {
        int xa1 = odd ? (i + 1) & M : (i - 1) & M;
        int xb0 = odd ? (i - 1) & M : (i + 1) & M;
        int xb1 = odd ? (i - 2) & M : (i + 2) & M;
        int ca = (i - 1) & M;
        int cb = odd ? (i - 2) & M : i;
        float4 a4 = g_C[253 * NN + ca];
        float4 b4 = g_C[253 * NN + cb];
        float4 d4 = g_C[254 * NN + i];
#pragma unroll
        for (int r = 0; r < RB; r++) {
            float2 ma = cfma4(A[r][i], A[r][xa1], a4);
            float2 mb = cfma4(A[r][xb0], A[r][xb1], b4);
            Bx[r][i] = cfma4(ma, mb, d4);
        }
        __syncthreads();
        float2 (*t_)[NN] = A; A = Bx; Bx = t_;
    }

    // ---- layer 255 (s=+1)
    {
        float4 cL = g_C[255 * NN + i];
        int ia = (i + 1) & M;
        int ib = ((i ^ 1) + 1) & M;
#pragma unroll
        for (int r = 0; r < RB; r++)
            Bx[r][i] = cfma4(A[r][ia], A[r][ib], cL);
        __syncthreads();
        float2 (*t_)[NN] = A; A = Bx; Bx = t_;
    }

    auto store_b = [](__nv_bfloat16* img, int n, int k, __nv_bfloat16 v) {
        uint32_t off = ((uint32_t)k >> 5) * 16384u + SWZ64((uint32_t)(n * 64 + (k & 31) * 2));
        *(__nv_bfloat16*)((char*)img + off) = v;
    };

    int src = (i - 1) & M;
#pragma unroll
    for (int r = 0; r < RB; r++) {
        float2 w = A[r][src];
        int k = r0 + r, n = i;
        __nv_bfloat16 hr = __float2bfloat16(w.x);
        __nv_bfloat16 lr = __float2bfloat16(w.x - __bfloat162float(hr));
        __nv_bfloat16 hi = __float2bfloat16(w.y);
        __nv_bfloat16 li = __float2bfloat16(w.y - __bfloat162float(hi));
        store_b(g_Wrh, n, k, hr);
        store_b(g_Wrl, n, k, lr);
        store_b(g_Wih, n, k, hi);
        store_b(g_Wil, n, k, li);
    }
}

// ---------------- kernel 2.5: no-op spacer ----------------
__global__ void probe_kernel() {}

// ---------------- kernel 3: tcgen05 cg2 GEMM, 3-stage ring, split last commit ----
#define KC 32
#define SMEM_TMEM 0
#define MB_FULL(s)  (16 + (s) * 8)
#define MB_EMPTY(s) (40 + (s) * 8)
#define MB_LEAD(s)  (64 + (s) * 8)
#define MB_DONE     88
#define MB_R        96
#define XR_H 0
#define XR_L 8192
#define XI_H 16384
#define XI_L 24576
#define WR_H 32768
#define WR_L 40960
#define WI_H 49152
#define WI_L 57344
#define STAGE_SZ 65536
#define STAGE_BASE(s) (1024 + (s) * STAGE_SZ)
#define SMEM_TOTAL (1024 + 3 * STAGE_SZ)
#define NSTG 3

__global__ __launch_bounds__(256, 1) __cluster_dims__(2, 1, 1)
void gemm_tc_kernel(const float* __restrict__ xre, const float* __restrict__ xim,
                    float* __restrict__ out) {
#if HAS_TC
    extern __shared__ char smem[];
    const uint32_t sb = smem_u32(smem);
    int tid = threadIdx.x, wid = tid >> 5, lane = tid & 31;
    int m0 = blockIdx.x * 128;
    uint32_t rank = cluster_rank();

    if (wid == 4) TCGEN05_ALLOC_CG2(sb + SMEM_TMEM, 512);
    if (tid == 0) {
#pragma unroll
        for (int s = 0; s < NSTG; ++s) {
            MBARRIER_INIT(sb + MB_FULL(s), 5);
            MBARRIER_INIT(sb + MB_EMPTY(s), 1);
            MBARRIER_INIT(sb + MB_LEAD(s), 2);
        }
        MBARRIER_INIT(sb + MB_DONE, 1);
        MBARRIER_INIT(sb + MB_R, 1);
    }
    __syncthreads();
    CLUSTER_SYNC();
    uint32_t tmem;
    asm volatile("ld.shared.b32 %0, [%1];" : "=r"(tmem) : "r"(sb + SMEM_TMEM));

    if (wid < 4) {
        // ---- A producer: register-prefetched fp32 -> bf16 hi/lo
        float4 buf[16];
#pragma unroll
        for (int j = 0; j < 16; ++j) {
            int pl = j >> 3;
            int g = (j & 7) * 128 + tid;
            int rr = g >> 3, f4 = g & 7;
            const float* plane = pl ? xim : xre;
            buf[j] = *(const float4*)(plane + (size_t)(m0 + rr) * NN + f4 * 4);
        }
        for (int it = 0; it < 8; ++it) {
            int s = it % NSTG;
            if (it >= NSTG) MBARRIER_WAIT_PARITY(sb + MB_EMPTY(s), ((it - NSTG) / NSTG) & 1);
            uint32_t stage = sb + STAGE_BASE(s);
            int kcn = (it + 1) * KC;
            bool more = (it < 7);
#pragma unroll
            for (int j = 0; j < 16; ++j) {
                int pl = j >> 3;
                int g = (j & 7) * 128 + tid;
                int rr = g >> 3, f4 = g & 7;
                float4 v = buf[j];
                if (more) {
                    const float* plane = pl ? xim : xre;
                    buf[j] = *(const float4*)(plane + (size_t)(m0 + rr) * NN + kcn + f4 * 4);
                }
                BU h0, h1, l0, l1;
                h0.h = __floats2bfloat162_rn(v.x, v.y);
                h1.h = __floats2bfloat162_rn(v.z, v.w);
                float2 f0 = __bfloat1622float2(h0.h), f1 = __bfloat1622float2(h1.h);
                l0.h = __floats2bfloat162_rn(v.x - f0.x, v.y - f0.y);
                l1.h = __floats2bfloat162_rn(v.z - f1.x, v.w - f1.y);
                uint32_t off = SWZ64((uint32_t)(rr * 64 + f4 * 8));
                uint32_t hdst = stage + (pl ? XI_H : XR_H) + off;
                uint32_t ldst = stage + (pl ? XI_L : XR_L) + off;
                asm volatile("st.shared.v2.b32 [%0], {%1,%2};" :: "r"(hdst), "r"(h0.u), "r"(h1.u) : "memory");
                asm volatile("st.shared.v2.b32 [%0], {%1,%2};" :: "r"(ldst), "r"(l0.u), "r"(l1.u) : "memory");
            }
            FENCE_ASYNC_SHARED();
            __syncwarp();
            if (lane == 0) MBARRIER_ARRIVE(sb + MB_FULL(s));
        }
    } else if (wid == 5) {
        // ---- B producer: this CTA's half of each image
        for (int it = 0; it < 8; ++it) {
            int s = it % NSTG;
            if (it >= NSTG) MBARRIER_WAIT_PARITY(sb + MB_EMPTY(s), ((it - NSTG) / NSTG) & 1);
            if (elect_one_pred()) {
                uint32_t mb = sb + MB_FULL(s);
                uint32_t stage = sb + STAGE_BASE(s);
                size_t co = (size_t)it * 16384 + (size_t)rank * 8192;
                MBARRIER_EXPECT_TX(mb, 32768);
                CP_ASYNC_BULK(stage + WR_H, (const char*)g_Wrh + co, 8192, mb);
                CP_ASYNC_BULK(stage + WR_L, (const char*)g_Wrl + co, 8192, mb);
                CP_ASYNC_BULK(stage + WI_H, (const char*)g_Wih + co, 8192, mb);
                CP_ASYNC_BULK(stage + WI_L, (const char*)g_Wil + co, 8192, mb);
            }
        }
    } else if (wid == 6) {
        // ---- relay: forward local readiness to leader
        for (int it = 0; it < 8; ++it) {
            int s = it % NSTG;
            MBARRIER_WAIT_PARITY(sb + MB_FULL(s), (it / NSTG) & 1);
            if (elect_one_pred()) MBARRIER_ARRIVE_LEADER(sb + MB_LEAD(s));
        }
    } else if (wid == 4 && rank == 0) {
        // ---- MMA warp (leader): interleaved Yr/Yi chains; stage 7 commits split.
        const uint32_t IDESC = (1u << 4) | (1u << 7) | (1u << 10) | (32u << 17) | (16u << 24);
        const uint32_t NEG_A = 1u << 13;
        const uint32_t aoffs[6] = {XR_H, XR_L, XR_H, XI_H, XI_L, XI_H};
        const uint32_t boffr[6] = {WR_H, WR_H, WR_L, WI_H, WI_H, WI_L};   // Yr (g>=3: neg A)
        const uint32_t boffi[6] = {WI_H, WI_H, WI_L, WR_H, WR_H, WR_L};   // Yi
        uint64_t dbase[NSTG];
#pragma unroll
        for (int s = 0; s < NSTG; ++s) dbase[s] = make_desc_sw64(sb + STAGE_BASE(s));
        for (int it = 0; it < 8; ++it) {
            int s = it % NSTG;
            MBARRIER_WAIT_PARITY_CLU(sb + MB_LEAD(s), (it / NSTG) & 1);
            if (elect_one_pred()) {
                uint64_t db = dbase[s];
                if (it < 7) {
#pragma unroll
                    for (int g = 0; g < 6; ++g) {
                        uint32_t idr = IDESC | ((g >= 3) ? NEG_A : 0u);
#pragma unroll
                        for (int kk = 0; kk < 2; ++kk) {
                            uint64_t ad = db + (aoffs[g] >> 4) + kk * 2;
                            uint32_t en = !(it == 0 && g == 0 && kk == 0);
                            mma_f16_ss_cg2(tmem,       ad, db + (boffr[g] >> 4) + kk * 2, idr,   en);
                            mma_f16_ss_cg2(tmem + 256, ad, db + (boffi[g] >> 4) + kk * 2, IDESC, en);
                        }
                    }
                    TCGEN05_COMMIT_MC_CG2(sb + MB_EMPTY(s), 0x3);
                } else {
                    // last stage: all Yr first -> MB_R, then Yi -> MB_DONE
#pragma unroll
                    for (int g = 0; g < 6; ++g) {
                        uint32_t idr = IDESC | ((g >= 3) ? NEG_A : 0u);
#pragma unroll
                        for (int kk = 0; kk < 2; ++kk)
                            mma_f16_ss_cg2(tmem, db + (aoffs[g] >> 4) + kk * 2,
                                           db + (boffr[g] >> 4) + kk * 2, idr, 1u);
                    }
                    TCGEN05_COMMIT_MC_CG2(sb + MB_R, 0x3);
#pragma unroll
                    for (int g = 0; g < 6; ++g) {
#pragma unroll
                        for (int kk = 0; kk < 2; ++kk)
                            mma_f16_ss_cg2(tmem + 256, db + (aoffs[g] >> 4) + kk * 2,
                                           db + (boffi[g] >> 4) + kk * 2, IDESC, 1u);
                    }
                    TCGEN05_COMMIT_MC_CG2(sb + MB_DONE, 0x3);
                }
            }
        }
    }

    // ---- epilogue: WG0 (Yr, cols 0-255) can start as soon as MB_R fires
    {
        int wg = tid >> 7;
        if (wg == 0) { MBARRIER_WAIT_PARITY(sb + MB_R, 0); }
        else         { MBARRIER_WAIT_PARITY(sb + MB_DONE, 0); }
        TCGEN05_FENCE_AFTER();
        int wt = tid & 127;
        int m = m0 + wt;
        float* dst = out + (size_t)wg * BB * NN + (size_t)m * NN;
        uint32_t colbase = tmem + wg * 256;
#pragma unroll
        for (int c = 0; c < 8; ++c) {
            uint32_t r[32];
            TCGEN05_LD_32X32B_X32(r, colbase + c * 32);
            TCGEN05_WAIT_LD();
            float4* d4 = (float4*)(dst + c * 32);
#pragma unroll
            for (int q = 0; q < 8; ++q)
                d4[q] = make_float4(__uint_as_float(r[4 * q]), __uint_as_float(r[4 * q + 1]),
                                    __uint_as_float(r[4 * q + 2]), __uint_as_float(r[4 * q + 3]));
        }
    }
    __syncthreads();
    if (wid == 4) {
        TCGEN05_RELINQ_CG2();
        TCGEN05_DEALLOC_CG2(tmem, 512);
    }
    CLUSTER_SYNC();
#endif  // HAS_TC
}

// ---------------- launch ----------------
extern "C" void kernel_launch(void* const* d_in, const int* in_sizes, int n_in,
                              void* d_out, int out_size) {
    const float* x_re  = (const float*)d_in[0];
    const float* x_im  = (const float*)d_in[1];
    const float* theta = (const float*)d_in[2];
    const float* phi   = (const float*)d_in[3];
    const float* gamma = (const float*)d_in[4];
    float* out = (float*)d_out;

    cudaFuncSetAttribute(gemm_tc_kernel, cudaFuncAttributeMaxDynamicSharedMemorySize, SMEM_TOTAL);

    coeff_kernel<<<LL, NN>>>(theta, phi);
    build_w_kernel<<<NN / RB, NN>>>(gamma);
    probe_kernel<<<1, 32>>>();
    gemm_tc_kernel<<<BB / 128, 256, SMEM_TOTAL>>>(x_re, x_im, out);
}

// round 13
// speedup vs baseline: 1.2582x; 1.2582x over previous
#include <cuda_runtime.h>
#include <cuda_bf16.h>
#include <cstdint>

#define NN 256
#define LL 256
#define BB 16384

#if defined(__CUDA_ARCH_FEAT_SM103_ALL) || defined(__CUDA_ARCH_FEAT_SM100_ALL) || defined(__CUDA_ARCH_FEAT_SM101_ALL)
#define HAS_TC 1
#else
#define HAS_TC 0
#endif

typedef unsigned long long u64;

// ---------------- scratch ----------------
__device__ float4 g_C[LL * NN];   // packed coeffs (diag.x, diag.y, off.x, off.y)
__device__ __align__(128) __nv_bfloat16 g_Wrh[256 * 256];
__device__ __align__(128) __nv_bfloat16 g_Wrl[256 * 256];
__device__ __align__(128) __nv_bfloat16 g_Wih[256 * 256];
__device__ __align__(128) __nv_bfloat16 g_Wil[256 * 256];

// ---------------- common helpers ----------------
__device__ __forceinline__ uint32_t smem_u32(const void* p) {
    uint32_t a;
    asm("{ .reg .u64 t; cvta.to.shared.u64 t, %1; cvt.u32.u64 %0, t; }" : "=r"(a) : "l"(p));
    return a;
}
__device__ __forceinline__ float2 cmul(float2 a, float2 b) {
    return make_float2(a.x * b.x - a.y * b.y, a.x * b.y + a.y * b.x);
}
union BU { __nv_bfloat162 h; uint32_t u; };
union F2U { float2 f; u64 u; };

#define FMA_F32X2(d, a, b) \
    asm("fma.rn.f32x2 %0, %1, %2, %0;" : "+l"(d) : "l"(a), "l"(b))
#define MUL_F32X2(d, a, b) \
    asm("mul.rn.f32x2 %0, %1, %2;" : "=l"(d) : "l"(a), "l"(b))
__device__ __forceinline__ u64 pack2(float lo, float hi) {
    u64 r; asm("mov.b64 %0, {%1,%2};" : "=l"(r) : "f"(lo), "f"(hi)); return r;
}
__device__ __forceinline__ u64 dup2(float x) {
    u64 r; asm("mov.b64 %0, {%1,%1};" : "=l"(r) : "f"(x)); return r;
}
// complex step: y = v0*d + v1*o, d=(c.x,c.y), o=(c.z,c.w)
__device__ __forceinline__ float2 cfma4(float2 v0, float2 v1, float4 c) {
    u64 w;
    MUL_F32X2(w, dup2(v0.x), pack2(c.x, c.y));
    FMA_F32X2(w, dup2(v0.y), pack2(-c.y, c.x));
    FMA_F32X2(w, dup2(v1.x), pack2(c.z, c.w));
    FMA_F32X2(w, dup2(v1.y), pack2(-c.w, c.z));
    F2U cv; cv.u = w; return cv.f;
}

// ---------------- tcgen05 / async helpers ----------------
#define TCGEN05_ALLOC_CG2(sa, n) \
    asm volatile("tcgen05.alloc.cta_group::2.sync.aligned.shared::cta.b32 [%0], %1;" :: "r"((uint32_t)(sa)), "r"((uint32_t)(n)) : "memory")
#define TCGEN05_DEALLOC_CG2(t, n) \
    asm volatile("tcgen05.dealloc.cta_group::2.sync.aligned.b32 %0, %1;" :: "r"(t), "r"((uint32_t)(n)))
#define TCGEN05_RELINQ_CG2() \
    asm volatile("tcgen05.relinquish_alloc_permit.cta_group::2.sync.aligned;")
#define TCGEN05_COMMIT_MC_CG2(mb, mask) \
    asm volatile("tcgen05.commit.cta_group::2.mbarrier::arrive::one.shared::cluster.multicast::cluster.b64 [%0], %1;" \
        :: "r"((uint32_t)(mb)), "h"((uint16_t)(mask)) : "memory")
#define TCGEN05_WAIT_LD() asm volatile("tcgen05.wait::ld.sync.aligned;" ::: "memory")
#define TCGEN05_FENCE_AFTER() asm volatile("tcgen05.fence::after_thread_sync;" ::: "memory")
#define FENCE_ASYNC_SHARED() asm volatile("fence.proxy.async.shared::cta;" ::: "memory")
#define CLUSTER_SYNC() do { \
    asm volatile("barrier.cluster.arrive.aligned;" ::: "memory"); \
    asm volatile("barrier.cluster.wait.aligned;" ::: "memory"); \
} while (0)

#define MBARRIER_INIT(mb, cnt) \
    asm volatile("mbarrier.init.shared.b64 [%0], %1;" :: "r"((uint32_t)(mb)), "r"((uint32_t)(cnt)) : "memory")
#define MBARRIER_ARRIVE(mb) \
    asm volatile("mbarrier.arrive.shared.b64 _, [%0];" :: "r"((uint32_t)(mb)) : "memory")
#define MBARRIER_ARRIVE_LEADER(mb) \
    asm volatile("{\n\t.reg .b32 la;\n\tand.b32 la, %0, 0xFEFFFFFF;\n\tmbarrier.arrive.shared::cluster.b64 _, [la];\n\t}" \
        :: "r"((uint32_t)(mb)) : "memory")
#define MBARRIER_EXPECT_TX(mb, tx) \
    asm volatile("mbarrier.arrive.expect_tx.shared.b64 _, [%0], %1;" :: "r"((uint32_t)(mb)), "r"((uint32_t)(tx)) : "memory")
#define MBARRIER_WAIT_PARITY(mb, ph) do { \
    uint32_t _mb = (uint32_t)(mb), _ph = (uint32_t)(ph), _done; \
    asm volatile("{\n\t.reg .pred p;\n\tmbarrier.try_wait.parity.acquire.cta.shared::cta.b64 p, [%1], %2;\n\tselp.b32 %0, 1, 0, p;\n\t}" \
        : "=r"(_done) : "r"(_mb), "r"(_ph) : "memory"); \
    if (!_done) { \
        asm volatile("{\n\t.reg .pred P1;\n\tWL_%=:\n\tmbarrier.try_wait.parity.acquire.cta.shared::cta.b64 P1, [%0], %1, 0x989680;\n\t@P1 bra.uni WD_%=;\n\tbra.uni WL_%=;\n\tWD_%=:\n\t}" \
            :: "r"(_mb), "r"(_ph) : "memory"); \
    } } while (0)
#define MBARRIER_WAIT_PARITY_CLU(mb, ph) do { \
    uint32_t _mb = (uint32_t)(mb), _ph = (uint32_t)(ph), _done; \
    asm volatile("{\n\t.reg .pred p;\n\tmbarrier.try_wait.parity.acquire.cluster.shared::cta.b64 p, [%1], %2;\n\tselp.b32 %0, 1, 0, p;\n\t}" \
        : "=r"(_done) : "r"(_mb), "r"(_ph) : "memory"); \
    if (!_done) { \
        asm volatile("{\n\t.reg .pred P1;\n\tWL_%=:\n\tmbarrier.try_wait.parity.acquire.cluster.shared::cta.b64 P1, [%0], %1, 0x989680;\n\t@P1 bra.uni WD_%=;\n\tbra.uni WL_%=;\n\tWD_%=:\n\t}" \
            :: "r"(_mb), "r"(_ph) : "memory"); \
    } } while (0)

#define CP_ASYNC_BULK(dst, src, bytes, mb) \
    asm volatile("cp.async.bulk.shared::cluster.global.mbarrier::complete_tx::bytes [%0], [%1], %2, [%3];" \
        :: "r"((uint32_t)(dst)), "l"(src), "r"((uint32_t)(bytes)), "r"((uint32_t)(mb)) : "memory")

#define TCGEN05_LD_32X32B_X32(r, ta) \
    asm volatile("tcgen05.ld.sync.aligned.32x32b.x32.b32 " \
        "{%0,%1,%2,%3,%4,%5,%6,%7,%8,%9,%10,%11,%12,%13,%14,%15," \
        "%16,%17,%18,%19,%20,%21,%22,%23,%24,%25,%26,%27,%28,%29,%30,%31}, [%32];" \
        : "=r"((r)[0]), "=r"((r)[1]), "=r"((r)[2]), "=r"((r)[3]), "=r"((r)[4]), "=r"((r)[5]), "=r"((r)[6]), "=r"((r)[7]), \
          "=r"((r)[8]), "=r"((r)[9]), "=r"((r)[10]), "=r"((r)[11]), "=r"((r)[12]), "=r"((r)[13]), "=r"((r)[14]), "=r"((r)[15]), \
          "=r"((r)[16]), "=r"((r)[17]), "=r"((r)[18]), "=r"((r)[19]), "=r"((r)[20]), "=r"((r)[21]), "=r"((r)[22]), "=r"((r)[23]), \
          "=r"((r)[24]), "=r"((r)[25]), "=r"((r)[26]), "=r"((r)[27]), "=r"((r)[28]), "=r"((r)[29]), "=r"((r)[30]), "=r"((r)[31]) \
        : "r"(ta))

#define SWZ64(o) ((o) ^ (((o) >> 3) & 0x30))

#if HAS_TC
__device__ __forceinline__ uint32_t elect_one_pred() {
    uint32_t p;
    asm volatile("{\n\t.reg .pred p;\n\telect.sync _|p, 0xFFFFFFFF;\n\tselp.b32 %0, 1, 0, p;\n\t}" : "=r"(p));
    return p;
}
__device__ __forceinline__ uint32_t cluster_rank() {
    uint32_t r; asm("mov.u32 %0, %%cluster_ctarank;" : "=r"(r)); return r;
}
__device__ __forceinline__ uint64_t make_desc_sw64(uint32_t base) {
    return ((uint64_t)4 << 61) | ((uint64_t)1 << 46) | ((uint64_t)32 << 32) | ((uint64_t)1 << 16)
         | (uint64_t)((base >> 4) & 0x3FFF);
}
__device__ __forceinline__ void mma_f16_ss_cg2(uint32_t d, uint64_t ad, uint64_t bd,
                                               uint32_t idesc, uint32_t en) {
    asm volatile(
        "{\n\t.reg .pred p;\n\tsetp.ne.u32 p, %5, 0;\n\t"
        "tcgen05.mma.cta_group::2.kind::f16 [%0], %1, %2, %3, {%4,%4,%4,%4,%4,%4,%4,%4}, p;\n\t}"
        :: "r"(d), "l"(ad), "l"(bd), "r"(idesc), "r"(0u), "r"(en) : "memory");
}
#endif

// ---------------- kernel 1: per-layer MZI coefficients ----------------
__global__ void coeff_kernel(const float* __restrict__ theta,
                             const float* __restrict__ phi) {
    __shared__ float2 ips[NN];
    __shared__ float2 eps[NN];
    __shared__ float2 offs[NN];
    int l = blockIdx.x;
    int n = threadIdx.x;
    const float* th = theta + l * (NN / 2);
    const float* ph = phi + l * (NN / 2);

    {
        float ang = 0.5f * th[n >> 1];
        if (n & 1) ang = -ang;
        float s, c; sincosf(ang, &s, &c);
        ips[n] = make_float2(c, s);
        if (n & 1) eps[n] = make_float2(1.f, 0.f);
        else { float s2, c2; sincosf(ph[n >> 1], &s2, &c2); eps[n] = make_float2(c2, s2); }
    }
    __syncthreads();

    int nm = (n - 1) & (NN - 1), np = (n + 1) & (NN - 1);
    float2 p0 = ips[nm], p1 = ips[n], p2 = ips[np];
    float2 v = make_float2(2.f * p1.x - p2.x - p0.x, 2.f * p1.y - p2.y - p0.y);
    float2 u = make_float2(2.f * p1.x + p2.x + p0.x, 2.f * p1.y + p2.y + p0.y);
    float2 en = eps[n], ep = eps[nm];

    float2 diag = cmul(en, v); diag.x *= 0.25f; diag.y *= 0.25f;
    float2 iu = make_float2(-u.y, u.x);
    float2 off = cmul(ep, iu); off.x *= 0.25f; off.y *= 0.25f;

    offs[n ^ 1] = off;
    __syncthreads();
    float2 o = offs[n];
    g_C[l * NN + n] = make_float4(diag.x, diag.y, o.x, o.y);
}

// ---------------- kernel 2: compose W — fused layer pairs, RB=1, 256 CTAs ----------
#define RB 1
__global__ __launch_bounds__(NN) void build_w_kernel(const float* __restrict__ gamma) {
    __shared__ float2 bufA[NN];
    __shared__ float2 bufB[NN];
    int i = threadIdx.x;
    int j0 = blockIdx.x;              // this CTA's basis row
    const int M = NN - 1;
    int odd = i & 1;

    {
        float2 v = make_float2(0.f, 0.f);
        if (i == j0) { float s, c; sincosf(gamma[j0], &s, &c); v = make_float2(c, s); }
        bufA[i] = v;
    }

    // loop-invariant indices (all pairs share s1=+1, s2=-1)
    int xa1 = odd ? (i + 1) & M : (i - 1) & M;
    int xb0 = odd ? (i - 1) & M : (i + 1) & M;
    int xb1 = odd ? (i - 2) & M : (i + 2) & M;
    int ca = (i - 1) & M;
    int cb = odd ? (i - 2) & M : i;

    float4 c0 = g_C[i];
    float4 cL = g_C[255 * NN + i];

    // 2-deep pair-coeff queue (packed float4s)
    float4 qa[2], qb[2], q2[2];
#pragma unroll
    for (int p = 0; p < 2; p++) {
        qa[p] = g_C[(2 * p + 1) * NN + ca];
        qb[p] = g_C[(2 * p + 1) * NN + cb];
        q2[p] = g_C[(2 * p + 2) * NN + i];
    }
    __syncthreads();

    float2* A = bufA;
    float2* Bx = bufB;

    // ---- layer 0 (s=0)
    Bx[i] = cfma4(A[i], A[i ^ 1], c0);
    __syncthreads();
    { float2* t_ = A; A = Bx; Bx = t_; }

    // ---- 127 fused pairs
    for (int p = 0; p < 127; ++p) {
        int sl = p & 1;
        float4 a4 = qa[sl], b4 = qb[sl], d4 = q2[sl];
        if (p + 2 < 127) {
            int pp = p + 2;
            qa[sl] = g_C[(2 * pp + 1) * NN + ca];
            qb[sl] = g_C[(2 * pp + 1) * NN + cb];
            q2[sl] = g_C[(2 * pp + 2) * NN + i];
        }
        float2 ma = cfma4(A[i], A[xa1], a4);
        float2 mb = cfma4(A[xb0], A[xb1], b4);
        Bx[i] = cfma4(ma, mb, d4);
        __syncthreads();
        float2* t_ = A; A = Bx; Bx = t_;
    }

    // ---- layer 255 (s=+1)
    {
        int ia = (i + 1) & M;
        int ib = ((i ^ 1) + 1) & M;
        Bx[i] = cfma4(A[ia], A[ib], cL);
        __syncthreads();
        float2* t_ = A; A = Bx; Bx = t_;
    }

    auto store_b = [](__nv_bfloat16* img, int n, int k, __nv_bfloat16 v) {
        uint32_t off = ((uint32_t)k >> 5) * 16384u + SWZ64((uint32_t)(n * 64 + (k & 31) * 2));
        *(__nv_bfloat16*)((char*)img + off) = v;
    };

    int src = (i - 1) & M;
    {
        float2 w = A[src];           // W[k][n], k = j0, n = i
        int k = j0, n = i;
        __nv_bfloat16 hr = __float2bfloat16(w.x);
        __nv_bfloat16 lr = __float2bfloat16(w.x - __bfloat162float(hr));
        __nv_bfloat16 hi = __float2bfloat16(w.y);
        __nv_bfloat16 li = __float2bfloat16(w.y - __bfloat162float(hi));
        store_b(g_Wrh, n, k, hr);
        store_b(g_Wrl, n, k, lr);
        store_b(g_Wih, n, k, hi);
        store_b(g_Wil, n, k, li);
    }
}

// ---------------- kernel 3: tcgen05 cg2 GEMM, 3-stage ring, split last commit ----
#define KC 32
#define SMEM_TMEM 0
#define MB_FULL(s)  (16 + (s) * 8)
#define MB_EMPTY(s) (40 + (s) * 8)
#define MB_LEAD(s)  (64 + (s) * 8)
#define MB_DONE     88
#define MB_R        96
#define XR_H 0
#define XR_L 8192
#define XI_H 16384
#define XI_L 24576
#define WR_H 32768
#define WR_L 40960
#define WI_H 49152
#define WI_L 57344
#define STAGE_SZ 65536
#define STAGE_BASE(s) (1024 + (s) * STAGE_SZ)
#define SMEM_TOTAL (1024 + 3 * STAGE_SZ)
#define NSTG 3

__global__ __launch_bounds__(256, 1) __cluster_dims__(2, 1, 1)
void gemm_tc_kernel(const float* __restrict__ xre, const float* __restrict__ xim,
                    float* __restrict__ out) {
#if HAS_TC
    extern __shared__ char smem[];
    const uint32_t sb = smem_u32(smem);
    int tid = threadIdx.x, wid = tid >> 5, lane = tid & 31;
    int m0 = blockIdx.x * 128;
    uint32_t rank = cluster_rank();

    if (wid == 4) TCGEN05_ALLOC_CG2(sb + SMEM_TMEM, 512);
    if (tid == 0) {
#pragma unroll
        for (int s = 0; s < NSTG; ++s) {
            MBARRIER_INIT(sb + MB_FULL(s), 5);
            MBARRIER_INIT(sb + MB_EMPTY(s), 1);
            MBARRIER_INIT(sb + MB_LEAD(s), 2);
        }
        MBARRIER_INIT(sb + MB_DONE, 1);
        MBARRIER_INIT(sb + MB_R, 1);
    }
    __syncthreads();
    CLUSTER_SYNC();
    uint32_t tmem;
    asm volatile("ld.shared.b32 %0, [%1];" : "=r"(tmem) : "r"(sb + SMEM_TMEM));

    if (wid < 4) {
        // ---- A producer: register-prefetched fp32 -> bf16 hi/lo
        float4 buf[16];
#pragma unroll
        for (int j = 0; j < 16; ++j) {
            int pl = j >> 3;
            int g = (j & 7) * 128 + tid;
            int rr = g >> 3, f4 = g & 7;
            const float* plane = pl ? xim : xre;
            buf[j] = *(const float4*)(plane + (size_t)(m0 + rr) * NN + f4 * 4);
        }
        for (int it = 0; it < 8; ++it) {
            int s = it % NSTG;
            if (it >= NSTG) MBARRIER_WAIT_PARITY(sb + MB_EMPTY(s), ((it - NSTG) / NSTG) & 1);
            uint32_t stage = sb + STAGE_BASE(s);
            int kcn = (it + 1) * KC;
            bool more = (it < 7);
#pragma unroll
            for (int j = 0; j < 16; ++j) {
                int pl = j >> 3;
                int g = (j & 7) * 128 + tid;
                int rr = g >> 3, f4 = g & 7;
                float4 v = buf[j];
                if (more) {
                    const float* plane = pl ? xim : xre;
                    buf[j] = *(const float4*)(plane + (size_t)(m0 + rr) * NN + kcn + f4 * 4);
                }
                BU h0, h1, l0, l1;
                h0.h = __floats2bfloat162_rn(v.x, v.y);
                h1.h = __floats2bfloat162_rn(v.z, v.w);
                float2 f0 = __bfloat1622float2(h0.h), f1 = __bfloat1622float2(h1.h);
                l0.h = __floats2bfloat162_rn(v.x - f0.x, v.y - f0.y);
                l1.h = __floats2bfloat162_rn(v.z - f1.x, v.w - f1.y);
                uint32_t off = SWZ64((uint32_t)(rr * 64 + f4 * 8));
                uint32_t hdst = stage + (pl ? XI_H : XR_H) + off;
                uint32_t ldst = stage + (pl ? XI_L : XR_L) + off;
                asm volatile("st.shared.v2.b32 [%0], {%1,%2};" :: "r"(hdst), "r"(h0.u), "r"(h1.u) : "memory");
                asm volatile("st.shared.v2.b32 [%0], {%1,%2};" :: "r"(ldst), "r"(l0.u), "r"(l1.u) : "memory");
            }
            FENCE_ASYNC_SHARED();
            __syncwarp();
            if (lane == 0) MBARRIER_ARRIVE(sb + MB_FULL(s));
        }
    } else if (wid == 5) {
        // ---- B producer: this CTA's half of each image
        for (int it = 0; it < 8; ++it) {
            int s = it % NSTG;
            if (it >= NSTG) MBARRIER_WAIT_PARITY(sb + MB_EMPTY(s), ((it - NSTG) / NSTG) & 1);
            if (elect_one_pred()) {
                uint32_t mb = sb + MB_FULL(s);
                uint32_t stage = sb + STAGE_BASE(s);
                size_t co = (size_t)it * 16384 + (size_t)rank * 8192;
                MBARRIER_EXPECT_TX(mb, 32768);
                CP_ASYNC_BULK(stage + WR_H, (const char*)g_Wrh + co, 8192, mb);
                CP_ASYNC_BULK(stage + WR_L, (const char*)g_Wrl + co, 8192, mb);
                CP_ASYNC_BULK(stage + WI_H, (const char*)g_Wih + co, 8192, mb);
                CP_ASYNC_BULK(stage + WI_L, (const char*)g_Wil + co, 8192, mb);
            }
        }
    } else if (wid == 6) {
        // ---- relay: forward local readiness to leader
        for (int it = 0; it < 8; ++it) {
            int s = it % NSTG;
            MBARRIER_WAIT_PARITY(sb + MB_FULL(s), (it / NSTG) & 1);
            if (elect_one_pred()) MBARRIER_ARRIVE_LEADER(sb + MB_LEAD(s));
        }
    } else if (wid == 4 && rank == 0) {
        // ---- MMA warp (leader): interleaved Yr/Yi chains; stage 7 commits split.
        const uint32_t IDESC = (1u << 4) | (1u << 7) | (1u << 10) | (32u << 17) | (16u << 24);
        const uint32_t NEG_A = 1u << 13;
        const uint32_t aoffs[6] = {XR_H, XR_L, XR_H, XI_H, XI_L, XI_H};
        const uint32_t boffr[6] = {WR_H, WR_H, WR_L, WI_H, WI_H, WI_L};   // Yr (g>=3: neg A)
        const uint32_t boffi[6] = {WI_H, WI_H, WI_L, WR_H, WR_H, WR_L};   // Yi
        uint64_t dbase[NSTG];
#pragma unroll
        for (int s = 0; s < NSTG; ++s) dbase[s] = make_desc_sw64(sb + STAGE_BASE(s));
        for (int it = 0; it < 8; ++it) {
            int s = it % NSTG;
            MBARRIER_WAIT_PARITY_CLU(sb + MB_LEAD(s), (it / NSTG) & 1);
            if (elect_one_pred()) {
                uint64_t db = dbase[s];
                if (it < 7) {
#pragma unroll
                    for (int g = 0; g < 6; ++g) {
                        uint32_t idr = IDESC | ((g >= 3) ? NEG_A : 0u);
#pragma unroll
                        for (int kk = 0; kk < 2; ++kk) {
                            uint64_t ad = db + (aoffs[g] >> 4) + kk * 2;
                            uint32_t en = !(it == 0 && g == 0 && kk == 0);
                            mma_f16_ss_cg2(tmem,       ad, db + (boffr[g] >> 4) + kk * 2, idr,   en);
                            mma_f16_ss_cg2(tmem + 256, ad, db + (boffi[g] >> 4) + kk * 2, IDESC, en);
                        }
                    }
                    TCGEN05_COMMIT_MC_CG2(sb + MB_EMPTY(s), 0x3);
                } else {
#pragma unroll
                    for (int g = 0; g < 6; ++g) {
                        uint32_t idr = IDESC | ((g >= 3) ? NEG_A : 0u);
#pragma unroll
                        for (int kk = 0; kk < 2; ++kk)
                            mma_f16_ss_cg2(tmem, db + (aoffs[g] >> 4) + kk * 2,
                                           db + (boffr[g] >> 4) + kk * 2, idr, 1u);
                    }
                    TCGEN05_COMMIT_MC_CG2(sb + MB_R, 0x3);
#pragma unroll
                    for (int g = 0; g < 6; ++g) {
#pragma unroll
                        for (int kk = 0; kk < 2; ++kk)
                            mma_f16_ss_cg2(tmem + 256, db + (aoffs[g] >> 4) + kk * 2,
                                           db + (boffi[g] >> 4) + kk * 2, IDESC, 1u);
                    }
                    TCGEN05_COMMIT_MC_CG2(sb + MB_DONE, 0x3);
                }
            }
        }
    }

    // ---- epilogue: WG0 (Yr) starts as soon as MB_R fires
    {
        int wg = tid >> 7;
        if (wg == 0) { MBARRIER_WAIT_PARITY(sb + MB_R, 0); }
        else         { MBARRIER_WAIT_PARITY(sb + MB_DONE, 0); }
        TCGEN05_FENCE_AFTER();
        int wt = tid & 127;
        int m = m0 + wt;
        float* dst = out + (size_t)wg * BB * NN + (size_t)m * NN;
        uint32_t colbase = tmem + wg * 256;
#pragma unroll
        for (int c = 0; c < 8; ++c) {
            uint32_t r[32];
            TCGEN05_LD_32X32B_X32(r, colbase + c * 32);
            TCGEN05_WAIT_LD();
            float4* d4 = (float4*)(dst + c * 32);
#pragma unroll
            for (int q = 0; q < 8; ++q)
                d4[q] = make_float4(__uint_as_float(r[4 * q]), __uint_as_float(r[4 * q + 1]),
                                    __uint_as_float(r[4 * q + 2]), __uint_as_float(r[4 * q + 3]));
        }
    }
    __syncthreads();
    if (wid == 4) {
        TCGEN05_RELINQ_CG2();
        TCGEN05_DEALLOC_CG2(tmem, 512);
    }
    CLUSTER_SYNC();
#endif  // HAS_TC
}

// ---------------- launch ----------------
extern "C" void kernel_launch(void* const* d_in, const int* in_sizes, int n_in,
                              void* d_out, int out_size) {
    const float* x_re  = (const float*)d_in[0];
    const float* x_im  = (const float*)d_in[1];
    const float* theta = (const float*)d_in[2];
    const float* phi   = (const float*)d_in[3];
    const float* gamma = (const float*)d_in[4];
    float* out = (float*)d_out;

    cudaFuncSetAttribute(gemm_tc_kernel, cudaFuncAttributeMaxDynamicSharedMemorySize, SMEM_TOTAL);

    coeff_kernel<<<LL, NN>>>(theta, phi);
    build_w_kernel<<<NN, NN>>>(gamma);
    gemm_tc_kernel<<<BB / 128, 256, SMEM_TOTAL>>>(x_re, x_im, out);
}